// round 1
// baseline (speedup 1.0000x reference)
#include <cuda_runtime.h>
#include <math.h>

// Problem constants
#define BATCH   4
#define SEQ     2048
#define CDIM    1024
#define NHEAD   16
#define DHEAD   64
#define MROWS   (BATCH * SEQ)          // 8192
#define BH      (BATCH * NHEAD)        // 64

// Scratch (device globals; no allocations allowed)
__device__ float g_q[(size_t)BH * SEQ * DHEAD];   // [BH][T][D]  32MB
__device__ float g_k[(size_t)BH * SEQ * DHEAD];   // 32MB
__device__ float g_v[(size_t)BH * SEQ * DHEAD];   // 32MB
__device__ float g_y[(size_t)MROWS * CDIM];       // [B,T,C]     32MB

// ---------------------------------------------------------------------------
// GEMM: out[M,N] = A[M,1024] @ W[1024,N] + bias[N]
// 128x128 tile, BK=16, 256 threads, 8x8 micro-tile per thread.
// SCATTER=true: N=3072, scatter into g_q/g_k/g_v as [BH][T][D].
// SCATTER=false: N=1024, write dense to out.
// ---------------------------------------------------------------------------
template <int NTOT, bool SCATTER>
__global__ __launch_bounds__(256)
void gemm_bias(const float* __restrict__ A, const float* __restrict__ W,
               const float* __restrict__ bias, float* __restrict__ out)
{
    __shared__ float As[16][128];   // transposed: As[k][m]
    __shared__ float Bs[16][128];   // Bs[k][n]

    const int tid = threadIdx.x;
    const int tx = tid & 15;
    const int ty = tid >> 4;
    const int r0 = blockIdx.y * 128;
    const int c0 = blockIdx.x * 128;

    float acc[8][8];
#pragma unroll
    for (int i = 0; i < 8; i++)
#pragma unroll
        for (int j = 0; j < 8; j++) acc[i][j] = 0.f;

    for (int k0 = 0; k0 < 1024; k0 += 16) {
        // Load A tile (128 x 16) transposed into As
#pragma unroll
        for (int i = 0; i < 2; i++) {
            int li = tid + i * 256;             // 0..511 float4 slots
            int row = li >> 2;                  // 0..127
            int kc = (li & 3) * 4;              // 0,4,8,12
            float4 f = *(const float4*)(A + (size_t)(r0 + row) * 1024 + k0 + kc);
            As[kc + 0][row] = f.x;
            As[kc + 1][row] = f.y;
            As[kc + 2][row] = f.z;
            As[kc + 3][row] = f.w;
        }
        // Load B tile (16 x 128)
#pragma unroll
        for (int i = 0; i < 2; i++) {
            int li = tid + i * 256;             // 0..511 float4 slots
            int row = li >> 5;                  // 0..15
            int nc = (li & 31) * 4;             // 0..124
            float4 f = *(const float4*)(W + (size_t)(k0 + row) * NTOT + c0 + nc);
            *(float4*)&Bs[row][nc] = f;
        }
        __syncthreads();

#pragma unroll
        for (int k = 0; k < 16; k++) {
            float a[8], b[8];
            *(float4*)&a[0] = *(float4*)&As[k][ty * 8];
            *(float4*)&a[4] = *(float4*)&As[k][ty * 8 + 4];
            *(float4*)&b[0] = *(float4*)&Bs[k][tx * 8];
            *(float4*)&b[4] = *(float4*)&Bs[k][tx * 8 + 4];
#pragma unroll
            for (int i = 0; i < 8; i++)
#pragma unroll
                for (int j = 0; j < 8; j++)
                    acc[i][j] = fmaf(a[i], b[j], acc[i][j]);
        }
        __syncthreads();
    }

    // Epilogue
#pragma unroll
    for (int i = 0; i < 8; i++) {
        int m = r0 + ty * 8 + i;
#pragma unroll
        for (int j = 0; j < 8; j++) {
            int n = c0 + tx * 8 + j;
            float v = acc[i][j] + bias[n];
            if (SCATTER) {
                int which = n >> 10;            // 0=q,1=k,2=v
                int c = n & 1023;
                int h = c >> 6;
                int d = c & 63;
                int b = m >> 11;                // /2048
                int t = m & 2047;
                size_t idx = ((size_t)(b * NHEAD + h) * SEQ + t) * DHEAD + d;
                float* dst = (which == 0) ? g_q : (which == 1) ? g_k : g_v;
                dst[idx] = v;
            } else {
                out[(size_t)m * 1024 + n] = v;
            }
        }
    }
}

// ---------------------------------------------------------------------------
// Flash attention: grid (T/64, BH), 256 threads (16x16), fp32.
// Each CTA: one 64-row Q tile of one (b,h); streams K/V tiles of 64 rows,
// online softmax, O accumulated in registers (4x4 per thread).
// Smem: Qt [d][r] (transposed), Kt [d][c] (transposed, reused as P [r][s]),
//       V  [s][c] (natural). Pitch 68 floats.
// ---------------------------------------------------------------------------
#define PITCH 68
#define SMEM_ATTN (3 * 64 * PITCH * 4)

__global__ __launch_bounds__(256)
void attn_kernel()
{
    extern __shared__ float sm[];
    float* sQt = sm;                    // [64][PITCH] : sQt[d*PITCH + r]
    float* sKt = sQt + 64 * PITCH;      // [64][PITCH] : sKt[d*PITCH + c]; reused as P[r][s]
    float* sV  = sKt + 64 * PITCH;      // [64][PITCH] : sV[s*PITCH + c]

    const int qi = blockIdx.x;
    const int bh = blockIdx.y;
    const int tid = threadIdx.x;
    const int tx = tid & 15;
    const int ty = tid >> 4;
    const int q0 = qi * 64;

    const float* Qg = g_q + (size_t)bh * SEQ * DHEAD;
    const float* Kg = g_k + (size_t)bh * SEQ * DHEAD;
    const float* Vg = g_v + (size_t)bh * SEQ * DHEAD;

    // Load Q tile transposed: global row t, col d -> sQt[d][t-local]
#pragma unroll
    for (int i = 0; i < 4; i++) {
        int li = tid + i * 256;          // 0..1023 float4 slots
        int row = li >> 4;               // 0..63 (local t)
        int col = (li & 15) * 4;         // d
        float4 f = *(const float4*)(Qg + (size_t)(q0 + row) * 64 + col);
        sQt[(col + 0) * PITCH + row] = f.x;
        sQt[(col + 1) * PITCH + row] = f.y;
        sQt[(col + 2) * PITCH + row] = f.z;
        sQt[(col + 3) * PITCH + row] = f.w;
    }

    float m_i[4], l_i[4], o[4][4];
#pragma unroll
    for (int i = 0; i < 4; i++) {
        m_i[i] = -1e30f;
        l_i[i] = 0.f;
#pragma unroll
        for (int j = 0; j < 4; j++) o[i][j] = 0.f;
    }

    const float scale = 0.125f;   // 1/sqrt(64)

    for (int j = 0; j <= qi; j++) {
        const int k0 = j * 64;
        __syncthreads();   // Q visible (iter 0); prev iter's P/V reads done

        // Load K transposed + V natural
#pragma unroll
        for (int i = 0; i < 4; i++) {
            int li = tid + i * 256;
            int row = li >> 4;
            int col = (li & 15) * 4;
            float4 f = *(const float4*)(Kg + (size_t)(k0 + row) * 64 + col);
            sKt[(col + 0) * PITCH + row] = f.x;
            sKt[(col + 1) * PITCH + row] = f.y;
            sKt[(col + 2) * PITCH + row] = f.z;
            sKt[(col + 3) * PITCH + row] = f.w;
            float4 g = *(const float4*)(Vg + (size_t)(k0 + row) * 64 + col);
            *(float4*)&sV[row * PITCH + col] = g;
        }
        __syncthreads();

        // S = Q K^T  (rows = ty*4.., cols = tx*4..)
        float s[4][4];
#pragma unroll
        for (int i = 0; i < 4; i++)
#pragma unroll
            for (int jj = 0; jj < 4; jj++) s[i][jj] = 0.f;

#pragma unroll 4
        for (int d = 0; d < 64; d++) {
            float4 q4 = *(float4*)&sQt[d * PITCH + ty * 4];
            float4 k4 = *(float4*)&sKt[d * PITCH + tx * 4];
            float qv[4] = {q4.x, q4.y, q4.z, q4.w};
            float kv[4] = {k4.x, k4.y, k4.z, k4.w};
#pragma unroll
            for (int i = 0; i < 4; i++)
#pragma unroll
                for (int jj = 0; jj < 4; jj++)
                    s[i][jj] = fmaf(qv[i], kv[jj], s[i][jj]);
        }

        __syncthreads();   // everyone done reading sKt (about to overwrite with P)

        // Scale + causal mask (only diagonal tile has masked entries)
        if (j == qi) {
#pragma unroll
            for (int i = 0; i < 4; i++)
#pragma unroll
                for (int jj = 0; jj < 4; jj++)
                    s[i][jj] = (tx * 4 + jj > ty * 4 + i) ? -1e30f : s[i][jj] * scale;
        } else {
#pragma unroll
            for (int i = 0; i < 4; i++)
#pragma unroll
                for (int jj = 0; jj < 4; jj++)
                    s[i][jj] *= scale;
        }

        // Online softmax per row (row owned by 16 threads sharing ty -> half-warp)
#pragma unroll
        for (int i = 0; i < 4; i++) {
            float rmax = fmaxf(fmaxf(s[i][0], s[i][1]), fmaxf(s[i][2], s[i][3]));
#pragma unroll
            for (int off = 8; off > 0; off >>= 1)
                rmax = fmaxf(rmax, __shfl_xor_sync(0xffffffffu, rmax, off));
            float mn = fmaxf(m_i[i], rmax);
            float alpha = __expf(m_i[i] - mn);
            float rsum = 0.f;
#pragma unroll
            for (int jj = 0; jj < 4; jj++) {
                float p = __expf(s[i][jj] - mn);
                s[i][jj] = p;
                rsum += p;
            }
#pragma unroll
            for (int off = 8; off > 0; off >>= 1)
                rsum += __shfl_xor_sync(0xffffffffu, rsum, off);
            l_i[i] = l_i[i] * alpha + rsum;
            m_i[i] = mn;
#pragma unroll
            for (int jj = 0; jj < 4; jj++) o[i][jj] *= alpha;
        }

        // Write P natural [r][s] into sKt buffer (vector stores)
#pragma unroll
        for (int i = 0; i < 4; i++) {
            *(float4*)&sKt[(ty * 4 + i) * PITCH + tx * 4] =
                make_float4(s[i][0], s[i][1], s[i][2], s[i][3]);
        }
        __syncthreads();

        // O += P @ V
#pragma unroll 2
        for (int ss = 0; ss < 64; ss++) {
            float4 v4 = *(float4*)&sV[ss * PITCH + tx * 4];
            float vv[4] = {v4.x, v4.y, v4.z, v4.w};
            float p0 = sKt[(ty * 4 + 0) * PITCH + ss];
            float p1 = sKt[(ty * 4 + 1) * PITCH + ss];
            float p2 = sKt[(ty * 4 + 2) * PITCH + ss];
            float p3 = sKt[(ty * 4 + 3) * PITCH + ss];
#pragma unroll
            for (int jj = 0; jj < 4; jj++) {
                o[0][jj] = fmaf(p0, vv[jj], o[0][jj]);
                o[1][jj] = fmaf(p1, vv[jj], o[1][jj]);
                o[2][jj] = fmaf(p2, vv[jj], o[2][jj]);
                o[3][jj] = fmaf(p3, vv[jj], o[3][jj]);
            }
        }
    }

    // Epilogue: normalize and write y in [B,T,C] layout
    const int b = bh >> 4;
    const int h = bh & 15;
#pragma unroll
    for (int i = 0; i < 4; i++) {
        float inv = 1.f / l_i[i];
        int t = q0 + ty * 4 + i;
        float* yrow = g_y + ((size_t)(b * SEQ + t)) * CDIM + h * 64 + tx * 4;
        *(float4*)yrow = make_float4(o[i][0] * inv, o[i][1] * inv,
                                     o[i][2] * inv, o[i][3] * inv);
    }
}

// ---------------------------------------------------------------------------
extern "C" void kernel_launch(void* const* d_in, const int* in_sizes, int n_in,
                              void* d_out, int out_size)
{
    const float* x      = (const float*)d_in[0];
    const float* w_attn = (const float*)d_in[1];
    const float* b_attn = (const float*)d_in[2];
    const float* w_proj = (const float*)d_in[3];
    const float* b_proj = (const float*)d_in[4];
    float* out = (float*)d_out;

    cudaFuncSetAttribute(attn_kernel, cudaFuncAttributeMaxDynamicSharedMemorySize,
                         SMEM_ATTN);

    void* y_ptr = nullptr;
    cudaGetSymbolAddress(&y_ptr, g_y);

    // 1) QKV projection + scatter to [BH][T][D]
    dim3 g1(3072 / 128, MROWS / 128);
    gemm_bias<3072, true><<<g1, 256>>>(x, w_attn, b_attn, nullptr);

    // 2) Causal flash attention
    dim3 g2(SEQ / 64, BH);
    attn_kernel<<<g2, 256, SMEM_ATTN>>>();

    // 3) Output projection
    dim3 g3(1024 / 128, MROWS / 128);
    gemm_bias<1024, false><<<g3, 256>>>((const float*)y_ptr, w_proj, b_proj, out);
}

// round 3
// speedup vs baseline: 1.7139x; 1.7139x over previous
#include <cuda_runtime.h>
#include <cstdint>

// Problem constants
#define BATCH   4
#define SEQ     2048
#define CDIM    1024
#define NHEAD   16
#define DHEAD   64
#define MROWS   (BATCH * SEQ)          // 8192
#define BH      (BATCH * NHEAD)        // 64

// Scratch (device globals; no allocations allowed)
__device__ float g_q[(size_t)BH * SEQ * DHEAD];   // [BH][T][D]
__device__ float g_k[(size_t)BH * SEQ * DHEAD];
__device__ float g_v[(size_t)BH * SEQ * DHEAD];
__device__ float g_y[(size_t)MROWS * CDIM];       // [B,T,C], tf32-rounded
__device__ float g_xr[(size_t)MROWS * CDIM];      // x, tf32-rounded
__device__ float g_wt1[(size_t)3072 * 1024];      // w_attn^T, tf32-rounded
__device__ float g_wt2[(size_t)1024 * 1024];      // w_proj^T, tf32-rounded

// ---------------------------------------------------------------------------
// Helpers
// ---------------------------------------------------------------------------
__device__ __forceinline__ uint32_t smem_u32(const void* p) {
    uint32_t a;
    asm("{ .reg .u64 t; cvta.to.shared.u64 t, %1; cvt.u32.u64 %0, t; }" : "=r"(a) : "l"(p));
    return a;
}
__device__ __forceinline__ float to_tf32(float x) {
    float r;
    asm("cvt.rna.tf32.f32 %0, %1;" : "=f"(r) : "f"(x));
    return r;
}
__device__ __forceinline__ void cp16(uint32_t smem_dst, const void* gsrc) {
    asm volatile("cp.async.cg.shared.global [%0], [%1], 16;" :: "r"(smem_dst), "l"(gsrc));
}
#define CP_COMMIT() asm volatile("cp.async.commit_group;" ::: "memory")
#define CP_WAIT(N)  asm volatile("cp.async.wait_group %0;" :: "n"(N) : "memory")

// m16n8k8 tf32 MMA (row.col), fp32 accumulate
__device__ __forceinline__ void mma_tf32(float c[4], const float a[4], const float b[2]) {
    asm volatile(
        "mma.sync.aligned.m16n8k8.row.col.f32.tf32.tf32.f32 "
        "{%0,%1,%2,%3}, {%4,%5,%6,%7}, {%8,%9}, {%0,%1,%2,%3};\n"
        : "+f"(c[0]), "+f"(c[1]), "+f"(c[2]), "+f"(c[3])
        : "r"(__float_as_uint(a[0])), "r"(__float_as_uint(a[1])),
          "r"(__float_as_uint(a[2])), "r"(__float_as_uint(a[3])),
          "r"(__float_as_uint(b[0])), "r"(__float_as_uint(b[1])));
}

// ---------------------------------------------------------------------------
// Pre-pass kernels: tf32 rounding (+transpose for weights)
// ---------------------------------------------------------------------------
__global__ __launch_bounds__(256)
void round_copy(const float* __restrict__ src, float* __restrict__ dst)
{
    int i = blockIdx.x * blockDim.x + threadIdx.x;
    float4 v = ((const float4*)src)[i];
    v.x = to_tf32(v.x); v.y = to_tf32(v.y);
    v.z = to_tf32(v.z); v.w = to_tf32(v.w);
    ((float4*)dst)[i] = v;
}

__global__ __launch_bounds__(256)
void transpose_round(const float* __restrict__ W, float* __restrict__ WT, int N)
{
    __shared__ float tile[32][33];
    int n0 = blockIdx.x * 32;
    int k0 = blockIdx.y * 32;
    int tx = threadIdx.x, ty = threadIdx.y;     // 32 x 8
#pragma unroll
    for (int i = ty; i < 32; i += 8)
        tile[i][tx] = W[(size_t)(k0 + i) * N + n0 + tx];
    __syncthreads();
#pragma unroll
    for (int i = ty; i < 32; i += 8)
        WT[(size_t)(n0 + i) * 1024 + k0 + tx] = to_tf32(tile[tx][i]);
}

// ---------------------------------------------------------------------------
// tf32 mma.sync GEMM: out[M,N] = A[M,1024] @ W[1024,N] + bias
// A tf32-rounded row-major; BT = W^T [N][1024] tf32-rounded.
// 128x128 CTA tile, BK=16, 8 warps (2x4) of 64x32, cp.async double buffer.
// Smem tiles [128][20] fp32 (pitch 20 -> conflict-free fragment loads).
// ---------------------------------------------------------------------------
#define PITCH_G 20

template <bool SCATTER>
__global__ __launch_bounds__(256)
void gemm_mma(const float* __restrict__ A, const float* __restrict__ BT,
              const float* __restrict__ bias, float* __restrict__ out)
{
    __shared__ float sA[2][128 * PITCH_G];
    __shared__ float sB[2][128 * PITCH_G];

    const int tid = threadIdx.x;
    const int wid = tid >> 5;
    const int lane = tid & 31;
    const int wr = wid >> 2;         // 0..1  (warp row: 64 M each)
    const int wc = wid & 3;          // 0..3  (warp col: 32 N each)
    const int c0 = blockIdx.x * 128;
    const int r0 = blockIdx.y * 128;

    const float* Ab = A + (size_t)r0 * 1024;
    const float* Bb = BT + (size_t)c0 * 1024;

    float acc[4][4][4];
#pragma unroll
    for (int mt = 0; mt < 4; mt++)
#pragma unroll
        for (int nt = 0; nt < 4; nt++)
#pragma unroll
            for (int u = 0; u < 4; u++) acc[mt][nt][u] = 0.f;

    // cp.async staging of one BK=16 slab into buffer `buf`
    auto stage = [&](int c, int buf) {
        const int k0 = c * 16;
#pragma unroll
        for (int i = 0; i < 2; i++) {
            int slot = tid + i * 256;        // 0..511
            int row = slot >> 2;             // 0..127
            int kq = (slot & 3) * 4;         // 0,4,8,12
            cp16(smem_u32(&sA[buf][row * PITCH_G + kq]),
                 Ab + (size_t)row * 1024 + k0 + kq);
            cp16(smem_u32(&sB[buf][row * PITCH_G + kq]),
                 Bb + (size_t)row * 1024 + k0 + kq);
        }
        CP_COMMIT();
    };

    stage(0, 0);

    const int lr = lane >> 2;        // 0..7
    const int lk = lane & 3;         // 0..3

    for (int c = 0; c < 64; c++) {
        const int buf = c & 1;
        if (c < 63) stage(c + 1, buf ^ 1);
        if (c < 63) { CP_WAIT(1); } else { CP_WAIT(0); }
        __syncthreads();

        const float* tA = sA[buf];
        const float* tB = sB[buf];
#pragma unroll
        for (int ks = 0; ks < 2; ks++) {
            float a[4][4], b[4][2];
#pragma unroll
            for (int mt = 0; mt < 4; mt++) {
                int m = wr * 64 + mt * 16 + lr;
                a[mt][0] = tA[m * PITCH_G + ks * 8 + lk];
                a[mt][1] = tA[(m + 8) * PITCH_G + ks * 8 + lk];
                a[mt][2] = tA[m * PITCH_G + ks * 8 + 4 + lk];
                a[mt][3] = tA[(m + 8) * PITCH_G + ks * 8 + 4 + lk];
            }
#pragma unroll
            for (int nt = 0; nt < 4; nt++) {
                int n = wc * 32 + nt * 8 + lr;
                b[nt][0] = tB[n * PITCH_G + ks * 8 + lk];
                b[nt][1] = tB[n * PITCH_G + ks * 8 + 4 + lk];
            }
#pragma unroll
            for (int mt = 0; mt < 4; mt++)
#pragma unroll
                for (int nt = 0; nt < 4; nt++)
                    mma_tf32(acc[mt][nt], a[mt], b[nt]);
        }
        __syncthreads();
    }

    // Epilogue: c0/c1 at (m, n..n+1), c2/c3 at (m+8, n..n+1)
    const int lc = (lane & 3) * 2;
#pragma unroll
    for (int mt = 0; mt < 4; mt++) {
#pragma unroll
        for (int nt = 0; nt < 4; nt++) {
            int m = r0 + wr * 64 + mt * 16 + lr;
            int n = c0 + wc * 32 + nt * 8 + lc;
            float b0 = bias[n], b1 = bias[n + 1];
            float2 v0 = make_float2(acc[mt][nt][0] + b0, acc[mt][nt][1] + b1);
            float2 v1 = make_float2(acc[mt][nt][2] + b0, acc[mt][nt][3] + b1);
            if (SCATTER) {
                int which = n >> 10;
                int cc = n & 1023;
                int h = cc >> 6;
                int d = cc & 63;
                int bb = m >> 11;
                int t = m & 2047;
                float* dst = (which == 0) ? g_q : (which == 1) ? g_k : g_v;
                size_t base = (size_t)(bb * NHEAD + h) * SEQ;
                *(float2*)(dst + (base + t) * DHEAD + d) = v0;
                *(float2*)(dst + (base + t + 8) * DHEAD + d) = v1;
            } else {
                *(float2*)(out + (size_t)m * 1024 + n) = v0;
                *(float2*)(out + (size_t)(m + 8) * 1024 + n) = v1;
            }
        }
    }
}

// ---------------------------------------------------------------------------
// Flash attention (fp32 SIMT, unchanged from passing R1 kernel, epilogue
// additionally rounds to tf32 since g_y feeds the tf32 proj GEMM)
// ---------------------------------------------------------------------------
#define PITCH 68
#define SMEM_ATTN (3 * 64 * PITCH * 4)

__global__ __launch_bounds__(256)
void attn_kernel()
{
    extern __shared__ float smf[];
    float* sQt = smf;
    float* sKt = sQt + 64 * PITCH;
    float* sV  = sKt + 64 * PITCH;

    const int qi = blockIdx.x;
    const int bh = blockIdx.y;
    const int tid = threadIdx.x;
    const int tx = tid & 15;
    const int ty = tid >> 4;
    const int q0 = qi * 64;

    const float* Qg = g_q + (size_t)bh * SEQ * DHEAD;
    const float* Kg = g_k + (size_t)bh * SEQ * DHEAD;
    const float* Vg = g_v + (size_t)bh * SEQ * DHEAD;

#pragma unroll
    for (int i = 0; i < 4; i++) {
        int li = tid + i * 256;
        int row = li >> 4;
        int col = (li & 15) * 4;
        float4 f = *(const float4*)(Qg + (size_t)(q0 + row) * 64 + col);
        sQt[(col + 0) * PITCH + row] = f.x;
        sQt[(col + 1) * PITCH + row] = f.y;
        sQt[(col + 2) * PITCH + row] = f.z;
        sQt[(col + 3) * PITCH + row] = f.w;
    }

    float m_i[4], l_i[4], o[4][4];
#pragma unroll
    for (int i = 0; i < 4; i++) {
        m_i[i] = -1e30f;
        l_i[i] = 0.f;
#pragma unroll
        for (int j = 0; j < 4; j++) o[i][j] = 0.f;
    }

    const float scale = 0.125f;

    for (int j = 0; j <= qi; j++) {
        const int k0 = j * 64;
        __syncthreads();

#pragma unroll
        for (int i = 0; i < 4; i++) {
            int li = tid + i * 256;
            int row = li >> 4;
            int col = (li & 15) * 4;
            float4 f = *(const float4*)(Kg + (size_t)(k0 + row) * 64 + col);
            sKt[(col + 0) * PITCH + row] = f.x;
            sKt[(col + 1) * PITCH + row] = f.y;
            sKt[(col + 2) * PITCH + row] = f.z;
            sKt[(col + 3) * PITCH + row] = f.w;
            float4 g = *(const float4*)(Vg + (size_t)(k0 + row) * 64 + col);
            *(float4*)&sV[row * PITCH + col] = g;
        }
        __syncthreads();

        float s[4][4];
#pragma unroll
        for (int i = 0; i < 4; i++)
#pragma unroll
            for (int jj = 0; jj < 4; jj++) s[i][jj] = 0.f;

#pragma unroll 4
        for (int d = 0; d < 64; d++) {
            float4 q4 = *(float4*)&sQt[d * PITCH + ty * 4];
            float4 k4 = *(float4*)&sKt[d * PITCH + tx * 4];
            float qv[4] = {q4.x, q4.y, q4.z, q4.w};
            float kv[4] = {k4.x, k4.y, k4.z, k4.w};
#pragma unroll
            for (int i = 0; i < 4; i++)
#pragma unroll
                for (int jj = 0; jj < 4; jj++)
                    s[i][jj] = fmaf(qv[i], kv[jj], s[i][jj]);
        }

        __syncthreads();

        if (j == qi) {
#pragma unroll
            for (int i = 0; i < 4; i++)
#pragma unroll
                for (int jj = 0; jj < 4; jj++)
                    s[i][jj] = (tx * 4 + jj > ty * 4 + i) ? -1e30f : s[i][jj] * scale;
        } else {
#pragma unroll
            for (int i = 0; i < 4; i++)
#pragma unroll
                for (int jj = 0; jj < 4; jj++)
                    s[i][jj] *= scale;
        }

#pragma unroll
        for (int i = 0; i < 4; i++) {
            float rmax = fmaxf(fmaxf(s[i][0], s[i][1]), fmaxf(s[i][2], s[i][3]));
#pragma unroll
            for (int off = 8; off > 0; off >>= 1)
                rmax = fmaxf(rmax, __shfl_xor_sync(0xffffffffu, rmax, off));
            float mn = fmaxf(m_i[i], rmax);
            float alpha = __expf(m_i[i] - mn);
            float rsum = 0.f;
#pragma unroll
            for (int jj = 0; jj < 4; jj++) {
                float p = __expf(s[i][jj] - mn);
                s[i][jj] = p;
                rsum += p;
            }
#pragma unroll
            for (int off = 8; off > 0; off >>= 1)
                rsum += __shfl_xor_sync(0xffffffffu, rsum, off);
            l_i[i] = l_i[i] * alpha + rsum;
            m_i[i] = mn;
#pragma unroll
            for (int jj = 0; jj < 4; jj++) o[i][jj] *= alpha;
        }

#pragma unroll
        for (int i = 0; i < 4; i++) {
            *(float4*)&sKt[(ty * 4 + i) * PITCH + tx * 4] =
                make_float4(s[i][0], s[i][1], s[i][2], s[i][3]);
        }
        __syncthreads();

#pragma unroll 2
        for (int ss = 0; ss < 64; ss++) {
            float4 v4 = *(float4*)&sV[ss * PITCH + tx * 4];
            float vv[4] = {v4.x, v4.y, v4.z, v4.w};
            float p0 = sKt[(ty * 4 + 0) * PITCH + ss];
            float p1 = sKt[(ty * 4 + 1) * PITCH + ss];
            float p2 = sKt[(ty * 4 + 2) * PITCH + ss];
            float p3 = sKt[(ty * 4 + 3) * PITCH + ss];
#pragma unroll
            for (int jj = 0; jj < 4; jj++) {
                o[0][jj] = fmaf(p0, vv[jj], o[0][jj]);
                o[1][jj] = fmaf(p1, vv[jj], o[1][jj]);
                o[2][jj] = fmaf(p2, vv[jj], o[2][jj]);
                o[3][jj] = fmaf(p3, vv[jj], o[3][jj]);
            }
        }
    }

    const int b = bh >> 4;
    const int h = bh & 15;
#pragma unroll
    for (int i = 0; i < 4; i++) {
        float inv = 1.f / l_i[i];
        int t = q0 + ty * 4 + i;
        float* yrow = g_y + ((size_t)(b * SEQ + t)) * CDIM + h * 64 + tx * 4;
        *(float4*)yrow = make_float4(to_tf32(o[i][0] * inv), to_tf32(o[i][1] * inv),
                                     to_tf32(o[i][2] * inv), to_tf32(o[i][3] * inv));
    }
}

// ---------------------------------------------------------------------------
extern "C" void kernel_launch(void* const* d_in, const int* in_sizes, int n_in,
                              void* d_out, int out_size)
{
    const float* x      = (const float*)d_in[0];
    const float* w_attn = (const float*)d_in[1];
    const float* b_attn = (const float*)d_in[2];
    const float* w_proj = (const float*)d_in[3];
    const float* b_proj = (const float*)d_in[4];
    float* out = (float*)d_out;

    cudaFuncSetAttribute(attn_kernel, cudaFuncAttributeMaxDynamicSharedMemorySize,
                         SMEM_ATTN);

    void* y_ptr = nullptr;   cudaGetSymbolAddress(&y_ptr, g_y);
    void* xr_ptr = nullptr;  cudaGetSymbolAddress(&xr_ptr, g_xr);
    void* wt1_ptr = nullptr; cudaGetSymbolAddress(&wt1_ptr, g_wt1);
    void* wt2_ptr = nullptr; cudaGetSymbolAddress(&wt2_ptr, g_wt2);

    // 0) tf32-round x; transpose + round weights
    round_copy<<<(MROWS * CDIM / 4) / 256, 256>>>(x, (float*)xr_ptr);
    transpose_round<<<dim3(3072 / 32, 1024 / 32), dim3(32, 8)>>>(w_attn, (float*)wt1_ptr, 3072);
    transpose_round<<<dim3(1024 / 32, 1024 / 32), dim3(32, 8)>>>(w_proj, (float*)wt2_ptr, 1024);

    // 1) QKV projection (tf32 mma) + scatter to [BH][T][D]
    gemm_mma<true><<<dim3(3072 / 128, MROWS / 128), 256>>>(
        (const float*)xr_ptr, (const float*)wt1_ptr, b_attn, nullptr);

    // 2) Causal flash attention (fp32 SIMT)
    attn_kernel<<<dim3(SEQ / 64, BH), 256, SMEM_ATTN>>>();

    // 3) Output projection (tf32 mma)
    gemm_mma<false><<<dim3(1024 / 128, MROWS / 128), 256>>>(
        (const float*)y_ptr, (const float*)wt2_ptr, b_proj, out);
}

// round 4
// speedup vs baseline: 2.9229x; 1.7054x over previous
#include <cuda_runtime.h>
#include <cstdint>

// Problem constants
#define BATCH   4
#define SEQ     2048
#define CDIM    1024
#define NHEAD   16
#define DHEAD   64
#define MROWS   (BATCH * SEQ)          // 8192
#define BH      (BATCH * NHEAD)        // 64

// Scratch (device globals; no allocations allowed)
__device__ float g_q[(size_t)BH * SEQ * DHEAD];   // [BH][T][D]
__device__ float g_k[(size_t)BH * SEQ * DHEAD];
__device__ float g_v[(size_t)BH * SEQ * DHEAD];
__device__ float g_y[(size_t)MROWS * CDIM];       // [B,T,C], tf32-rounded
__device__ float g_xr[(size_t)MROWS * CDIM];      // x, tf32-rounded
__device__ float g_wt1[(size_t)3072 * 1024];      // w_attn^T, tf32-rounded
__device__ float g_wt2[(size_t)1024 * 1024];      // w_proj^T, tf32-rounded

// ---------------------------------------------------------------------------
// Helpers
// ---------------------------------------------------------------------------
__device__ __forceinline__ uint32_t smem_u32(const void* p) {
    uint32_t a;
    asm("{ .reg .u64 t; cvta.to.shared.u64 t, %1; cvt.u32.u64 %0, t; }" : "=r"(a) : "l"(p));
    return a;
}
__device__ __forceinline__ float to_tf32(float x) {
    float r;
    asm("cvt.rna.tf32.f32 %0, %1;" : "=f"(r) : "f"(x));
    return r;
}
__device__ __forceinline__ void cp16(uint32_t smem_dst, const void* gsrc) {
    asm volatile("cp.async.cg.shared.global [%0], [%1], 16;" :: "r"(smem_dst), "l"(gsrc));
}
#define CP_COMMIT() asm volatile("cp.async.commit_group;" ::: "memory")
#define CP_WAIT(N)  asm volatile("cp.async.wait_group %0;" :: "n"(N) : "memory")

// m16n8k8 tf32 MMA (row.col), fp32 accumulate
__device__ __forceinline__ void mma_tf32(float c[4], const float a[4], const float b[2]) {
    asm volatile(
        "mma.sync.aligned.m16n8k8.row.col.f32.tf32.tf32.f32 "
        "{%0,%1,%2,%3}, {%4,%5,%6,%7}, {%8,%9}, {%0,%1,%2,%3};\n"
        : "+f"(c[0]), "+f"(c[1]), "+f"(c[2]), "+f"(c[3])
        : "r"(__float_as_uint(a[0])), "r"(__float_as_uint(a[1])),
          "r"(__float_as_uint(a[2])), "r"(__float_as_uint(a[3])),
          "r"(__float_as_uint(b[0])), "r"(__float_as_uint(b[1])));
}

// ---------------------------------------------------------------------------
// Pre-pass kernels: tf32 rounding (+transpose for weights)
// ---------------------------------------------------------------------------
__global__ __launch_bounds__(256)
void round_copy(const float* __restrict__ src, float* __restrict__ dst)
{
    int i = blockIdx.x * blockDim.x + threadIdx.x;
    float4 v = ((const float4*)src)[i];
    v.x = to_tf32(v.x); v.y = to_tf32(v.y);
    v.z = to_tf32(v.z); v.w = to_tf32(v.w);
    ((float4*)dst)[i] = v;
}

__global__ __launch_bounds__(256)
void transpose_round(const float* __restrict__ W, float* __restrict__ WT, int N)
{
    __shared__ float tile[32][33];
    int n0 = blockIdx.x * 32;
    int k0 = blockIdx.y * 32;
    int tx = threadIdx.x, ty = threadIdx.y;     // 32 x 8
#pragma unroll
    for (int i = ty; i < 32; i += 8)
        tile[i][tx] = W[(size_t)(k0 + i) * N + n0 + tx];
    __syncthreads();
#pragma unroll
    for (int i = ty; i < 32; i += 8)
        WT[(size_t)(n0 + i) * 1024 + k0 + tx] = to_tf32(tile[tx][i]);
}

// ---------------------------------------------------------------------------
// tf32 mma.sync GEMM: out[M,N] = A[M,1024] @ W[1024,N] + bias
// (unchanged from passing R3 kernel)
// ---------------------------------------------------------------------------
#define PITCH_G 20

template <bool SCATTER>
__global__ __launch_bounds__(256)
void gemm_mma(const float* __restrict__ A, const float* __restrict__ BT,
              const float* __restrict__ bias, float* __restrict__ out)
{
    __shared__ float sA[2][128 * PITCH_G];
    __shared__ float sB[2][128 * PITCH_G];

    const int tid = threadIdx.x;
    const int wid = tid >> 5;
    const int lane = tid & 31;
    const int wr = wid >> 2;
    const int wc = wid & 3;
    const int c0 = blockIdx.x * 128;
    const int r0 = blockIdx.y * 128;

    const float* Ab = A + (size_t)r0 * 1024;
    const float* Bb = BT + (size_t)c0 * 1024;

    float acc[4][4][4];
#pragma unroll
    for (int mt = 0; mt < 4; mt++)
#pragma unroll
        for (int nt = 0; nt < 4; nt++)
#pragma unroll
            for (int u = 0; u < 4; u++) acc[mt][nt][u] = 0.f;

    auto stage = [&](int c, int buf) {
        const int k0 = c * 16;
#pragma unroll
        for (int i = 0; i < 2; i++) {
            int slot = tid + i * 256;
            int row = slot >> 2;
            int kq = (slot & 3) * 4;
            cp16(smem_u32(&sA[buf][row * PITCH_G + kq]),
                 Ab + (size_t)row * 1024 + k0 + kq);
            cp16(smem_u32(&sB[buf][row * PITCH_G + kq]),
                 Bb + (size_t)row * 1024 + k0 + kq);
        }
        CP_COMMIT();
    };

    stage(0, 0);

    const int lr = lane >> 2;
    const int lk = lane & 3;

    for (int c = 0; c < 64; c++) {
        const int buf = c & 1;
        if (c < 63) stage(c + 1, buf ^ 1);
        if (c < 63) { CP_WAIT(1); } else { CP_WAIT(0); }
        __syncthreads();

        const float* tA = sA[buf];
        const float* tB = sB[buf];
#pragma unroll
        for (int ks = 0; ks < 2; ks++) {
            float a[4][4], b[4][2];
#pragma unroll
            for (int mt = 0; mt < 4; mt++) {
                int m = wr * 64 + mt * 16 + lr;
                a[mt][0] = tA[m * PITCH_G + ks * 8 + lk];
                a[mt][1] = tA[(m + 8) * PITCH_G + ks * 8 + lk];
                a[mt][2] = tA[m * PITCH_G + ks * 8 + 4 + lk];
                a[mt][3] = tA[(m + 8) * PITCH_G + ks * 8 + 4 + lk];
            }
#pragma unroll
            for (int nt = 0; nt < 4; nt++) {
                int n = wc * 32 + nt * 8 + lr;
                b[nt][0] = tB[n * PITCH_G + ks * 8 + lk];
                b[nt][1] = tB[n * PITCH_G + ks * 8 + 4 + lk];
            }
#pragma unroll
            for (int mt = 0; mt < 4; mt++)
#pragma unroll
                for (int nt = 0; nt < 4; nt++)
                    mma_tf32(acc[mt][nt], a[mt], b[nt]);
        }
        __syncthreads();
    }

    const int lc = (lane & 3) * 2;
#pragma unroll
    for (int mt = 0; mt < 4; mt++) {
#pragma unroll
        for (int nt = 0; nt < 4; nt++) {
            int m = r0 + wr * 64 + mt * 16 + lr;
            int n = c0 + wc * 32 + nt * 8 + lc;
            float b0 = bias[n], b1 = bias[n + 1];
            float2 v0 = make_float2(acc[mt][nt][0] + b0, acc[mt][nt][1] + b1);
            float2 v1 = make_float2(acc[mt][nt][2] + b0, acc[mt][nt][3] + b1);
            if (SCATTER) {
                int which = n >> 10;
                int cc = n & 1023;
                int h = cc >> 6;
                int d = cc & 63;
                int bb = m >> 11;
                int t = m & 2047;
                float* dst = (which == 0) ? g_q : (which == 1) ? g_k : g_v;
                size_t base = (size_t)(bb * NHEAD + h) * SEQ;
                *(float2*)(dst + (base + t) * DHEAD + d) = v0;
                *(float2*)(dst + (base + t + 8) * DHEAD + d) = v1;
            } else {
                *(float2*)(out + (size_t)m * 1024 + n) = v0;
                *(float2*)(out + (size_t)(m + 8) * 1024 + n) = v1;
            }
        }
    }
}

// ---------------------------------------------------------------------------
// Tensor-core flash attention (tf32 mma.sync)
// grid (16, 64): one CTA per (q-tile of 128 rows, bh). 8 warps x 16 Q rows.
// Q fragments register-resident; K/V staged in smem natural [s][d] layout;
// P round-trips through per-warp-private smem (only __syncwarp needed).
// ---------------------------------------------------------------------------
#define AP 68
#define SMEM_ATTN ((64 + 64 + 128) * AP * 4)   // sK + sV + sP = 69,632 B

__global__ __launch_bounds__(256)
void attn_mma()
{
    extern __shared__ float sm[];
    float* sK = sm;                  // [64][AP]  K tile natural [s][d]
    float* sV = sK + 64 * AP;        // [64][AP]  V tile natural [s][d]
    float* sP = sV + 64 * AP;        // [128][AP] P [m][s], per-warp-private rows

    const int qi = (int)gridDim.x - 1 - (int)blockIdx.x;   // heavy tiles first
    const int bh = blockIdx.y;
    const int tid = threadIdx.x;
    const int wid = tid >> 5;
    const int lane = tid & 31;
    const int lr = lane >> 2;        // 0..7
    const int lk = lane & 3;         // 0..3
    const int warp_m = wid * 16;
    const int q0 = qi * 128;

    const float* Kg = g_k + (size_t)bh * SEQ * DHEAD;
    const float* Vg = g_v + (size_t)bh * SEQ * DHEAD;

    // Q fragments: A-frag per k-step (8 steps of k=8)
    float qf[8][4];
    {
        const float* Qw = g_q + ((size_t)bh * SEQ + q0 + warp_m) * DHEAD;
#pragma unroll
        for (int ks = 0; ks < 8; ks++) {
            qf[ks][0] = to_tf32(Qw[lr * 64 + ks * 8 + lk]);
            qf[ks][1] = to_tf32(Qw[(lr + 8) * 64 + ks * 8 + lk]);
            qf[ks][2] = to_tf32(Qw[lr * 64 + ks * 8 + 4 + lk]);
            qf[ks][3] = to_tf32(Qw[(lr + 8) * 64 + ks * 8 + 4 + lk]);
        }
    }

    float o[8][4];
#pragma unroll
    for (int nt = 0; nt < 8; nt++)
#pragma unroll
        for (int u = 0; u < 4; u++) o[nt][u] = 0.f;

    float m0 = -1e30f, m1 = -1e30f, l0 = 0.f, l1 = 0.f;
    const float scale = 0.125f;      // 1/sqrt(64)
    const int row0 = q0 + warp_m + lr;
    const int row1 = row0 + 8;

    float* Pr0 = &sP[(warp_m + lr) * AP];
    float* Pr1 = &sP[(warp_m + lr + 8) * AP];

    const int nkt = (qi + 1) * 2;
    for (int kt = 0; kt < nkt; kt++) {
        const int k0 = kt * 64;
        __syncthreads();             // prior PV reads of sK/sV done

        // Stage K and V tiles (64 x 64 each), tf32-rounded, natural layout
#pragma unroll
        for (int i = 0; i < 4; i++) {
            int slot = tid + i * 256;
            int row = slot >> 4;
            int c4 = (slot & 15) * 4;
            float4 kv = *(const float4*)(Kg + (size_t)(k0 + row) * 64 + c4);
            kv.x = to_tf32(kv.x); kv.y = to_tf32(kv.y);
            kv.z = to_tf32(kv.z); kv.w = to_tf32(kv.w);
            *(float4*)&sK[row * AP + c4] = kv;
            float4 vv = *(const float4*)(Vg + (size_t)(k0 + row) * 64 + c4);
            vv.x = to_tf32(vv.x); vv.y = to_tf32(vv.y);
            vv.z = to_tf32(vv.z); vv.w = to_tf32(vv.w);
            *(float4*)&sV[row * AP + c4] = vv;
        }
        __syncthreads();

        // Warps fully above the diagonal of this K tile have nothing to do
        if (k0 > q0 + warp_m + 15) continue;

        // S = Q K^T   (16 x 64 per warp)
        float s[8][4];
#pragma unroll
        for (int nt = 0; nt < 8; nt++)
#pragma unroll
            for (int u = 0; u < 4; u++) s[nt][u] = 0.f;

#pragma unroll
        for (int nt = 0; nt < 8; nt++) {
            const float* Kn = &sK[(nt * 8 + lr) * AP];
#pragma unroll
            for (int ks = 0; ks < 8; ks++) {
                float b[2] = {Kn[ks * 8 + lk], Kn[ks * 8 + 4 + lk]};
                mma_tf32(s[nt], qf[ks], b);
            }
        }

        // Scale + causal mask + row max
        const bool need_mask = (k0 + 63 > row0);   // tile may cross diagonal
        float rmax0 = -1e30f, rmax1 = -1e30f;
#pragma unroll
        for (int nt = 0; nt < 8; nt++) {
            const int cb = k0 + nt * 8 + 2 * lk;
            if (need_mask) {
                s[nt][0] = (cb     > row0) ? -1e30f : s[nt][0] * scale;
                s[nt][1] = (cb + 1 > row0) ? -1e30f : s[nt][1] * scale;
                s[nt][2] = (cb     > row1) ? -1e30f : s[nt][2] * scale;
                s[nt][3] = (cb + 1 > row1) ? -1e30f : s[nt][3] * scale;
            } else {
                s[nt][0] *= scale; s[nt][1] *= scale;
                s[nt][2] *= scale; s[nt][3] *= scale;
            }
            rmax0 = fmaxf(rmax0, fmaxf(s[nt][0], s[nt][1]));
            rmax1 = fmaxf(rmax1, fmaxf(s[nt][2], s[nt][3]));
        }
        rmax0 = fmaxf(rmax0, __shfl_xor_sync(0xffffffffu, rmax0, 1));
        rmax0 = fmaxf(rmax0, __shfl_xor_sync(0xffffffffu, rmax0, 2));
        rmax1 = fmaxf(rmax1, __shfl_xor_sync(0xffffffffu, rmax1, 1));
        rmax1 = fmaxf(rmax1, __shfl_xor_sync(0xffffffffu, rmax1, 2));

        const float mn0 = fmaxf(m0, rmax0);
        const float mn1 = fmaxf(m1, rmax1);
        const float a0 = __expf(m0 - mn0);
        const float a1 = __expf(m1 - mn1);
        m0 = mn0; m1 = mn1;

        float rs0 = 0.f, rs1 = 0.f;
#pragma unroll
        for (int nt = 0; nt < 8; nt++) {
            s[nt][0] = __expf(s[nt][0] - mn0);
            s[nt][1] = __expf(s[nt][1] - mn0);
            s[nt][2] = __expf(s[nt][2] - mn1);
            s[nt][3] = __expf(s[nt][3] - mn1);
            rs0 += s[nt][0] + s[nt][1];
            rs1 += s[nt][2] + s[nt][3];
        }
        rs0 += __shfl_xor_sync(0xffffffffu, rs0, 1);
        rs0 += __shfl_xor_sync(0xffffffffu, rs0, 2);
        rs1 += __shfl_xor_sync(0xffffffffu, rs1, 1);
        rs1 += __shfl_xor_sync(0xffffffffu, rs1, 2);
        l0 = l0 * a0 + rs0;
        l1 = l1 * a1 + rs1;

#pragma unroll
        for (int nt = 0; nt < 8; nt++) {
            o[nt][0] *= a0; o[nt][1] *= a0;
            o[nt][2] *= a1; o[nt][3] *= a1;
        }

        // P -> per-warp-private smem strip (tf32-rounded)
#pragma unroll
        for (int nt = 0; nt < 8; nt++) {
            *(float2*)&Pr0[nt * 8 + 2 * lk] =
                make_float2(to_tf32(s[nt][0]), to_tf32(s[nt][1]));
            *(float2*)&Pr1[nt * 8 + 2 * lk] =
                make_float2(to_tf32(s[nt][2]), to_tf32(s[nt][3]));
        }
        __syncwarp();

        // O += P @ V
#pragma unroll
        for (int ks = 0; ks < 8; ks++) {
            float ap[4];
            ap[0] = Pr0[ks * 8 + lk];
            ap[1] = Pr1[ks * 8 + lk];
            ap[2] = Pr0[ks * 8 + 4 + lk];
            ap[3] = Pr1[ks * 8 + 4 + lk];
#pragma unroll
            for (int nt = 0; nt < 8; nt++) {
                float b[2] = {sV[(ks * 8 + lk) * AP + nt * 8 + lr],
                              sV[(ks * 8 + 4 + lk) * AP + nt * 8 + lr]};
                mma_tf32(o[nt], ap, b);
            }
        }
        __syncwarp();
    }

    // Epilogue: normalize, tf32-round (feeds tf32 proj GEMM), write [B,T,C]
    const float inv0 = 1.f / l0;
    const float inv1 = 1.f / l1;
    const int b = bh >> 4;
    const int h = bh & 15;
    float* y0 = g_y + ((size_t)(b * SEQ + row0)) * CDIM + h * 64;
    float* y1 = g_y + ((size_t)(b * SEQ + row1)) * CDIM + h * 64;
#pragma unroll
    for (int nt = 0; nt < 8; nt++) {
        int d = nt * 8 + 2 * lk;
        *(float2*)(y0 + d) = make_float2(to_tf32(o[nt][0] * inv0),
                                         to_tf32(o[nt][1] * inv0));
        *(float2*)(y1 + d) = make_float2(to_tf32(o[nt][2] * inv1),
                                         to_tf32(o[nt][3] * inv1));
    }
}

// ---------------------------------------------------------------------------
extern "C" void kernel_launch(void* const* d_in, const int* in_sizes, int n_in,
                              void* d_out, int out_size)
{
    const float* x      = (const float*)d_in[0];
    const float* w_attn = (const float*)d_in[1];
    const float* b_attn = (const float*)d_in[2];
    const float* w_proj = (const float*)d_in[3];
    const float* b_proj = (const float*)d_in[4];
    float* out = (float*)d_out;

    cudaFuncSetAttribute(attn_mma, cudaFuncAttributeMaxDynamicSharedMemorySize,
                         SMEM_ATTN);

    void* y_ptr = nullptr;   cudaGetSymbolAddress(&y_ptr, g_y);
    void* xr_ptr = nullptr;  cudaGetSymbolAddress(&xr_ptr, g_xr);
    void* wt1_ptr = nullptr; cudaGetSymbolAddress(&wt1_ptr, g_wt1);
    void* wt2_ptr = nullptr; cudaGetSymbolAddress(&wt2_ptr, g_wt2);

    // 0) tf32-round x; transpose + round weights
    round_copy<<<(MROWS * CDIM / 4) / 256, 256>>>(x, (float*)xr_ptr);
    transpose_round<<<dim3(3072 / 32, 1024 / 32), dim3(32, 8)>>>(w_attn, (float*)wt1_ptr, 3072);
    transpose_round<<<dim3(1024 / 32, 1024 / 32), dim3(32, 8)>>>(w_proj, (float*)wt2_ptr, 1024);

    // 1) QKV projection (tf32 mma) + scatter to [BH][T][D]
    gemm_mma<true><<<dim3(3072 / 128, MROWS / 128), 256>>>(
        (const float*)xr_ptr, (const float*)wt1_ptr, b_attn, nullptr);

    // 2) Causal flash attention (tf32 mma)
    attn_mma<<<dim3(SEQ / 128, BH), 256, SMEM_ATTN>>>();

    // 3) Output projection (tf32 mma)
    gemm_mma<false><<<dim3(1024 / 128, MROWS / 128), 256>>>(
        (const float*)y_ptr, (const float*)wt2_ptr, b_proj, out);
}

// round 5
// speedup vs baseline: 3.4013x; 1.1637x over previous
#include <cuda_runtime.h>
#include <cstdint>

// Problem constants
#define BATCH   4
#define SEQ     2048
#define CDIM    1024
#define NHEAD   16
#define DHEAD   64
#define MROWS   (BATCH * SEQ)          // 8192
#define BH      (BATCH * NHEAD)        // 64

// Scratch (device globals; no allocations allowed)
__device__ float g_q[(size_t)BH * SEQ * DHEAD];   // [BH][T][D]
__device__ float g_k[(size_t)BH * SEQ * DHEAD];
__device__ float g_v[(size_t)BH * SEQ * DHEAD];
__device__ float g_y[(size_t)MROWS * CDIM];       // [B,T,C], tf32-rounded
__device__ float g_xr[(size_t)MROWS * CDIM];      // x, tf32-rounded
__device__ float g_wt1[(size_t)3072 * 1024];      // w_attn^T, tf32-rounded
__device__ float g_wt2[(size_t)1024 * 1024];      // w_proj^T, tf32-rounded

// ---------------------------------------------------------------------------
// Helpers
// ---------------------------------------------------------------------------
__device__ __forceinline__ uint32_t smem_u32(const void* p) {
    uint32_t a;
    asm("{ .reg .u64 t; cvta.to.shared.u64 t, %1; cvt.u32.u64 %0, t; }" : "=r"(a) : "l"(p));
    return a;
}
__device__ __forceinline__ float to_tf32(float x) {
    float r;
    asm("cvt.rna.tf32.f32 %0, %1;" : "=f"(r) : "f"(x));
    return r;
}
__device__ __forceinline__ void cp16(uint32_t smem_dst, const void* gsrc) {
    asm volatile("cp.async.cg.shared.global [%0], [%1], 16;" :: "r"(smem_dst), "l"(gsrc));
}
#define CP_COMMIT() asm volatile("cp.async.commit_group;" ::: "memory")
#define CP_WAIT(N)  asm volatile("cp.async.wait_group %0;" :: "n"(N) : "memory")

// m16n8k8 tf32 MMA (row.col), fp32 accumulate
__device__ __forceinline__ void mma_tf32(float c[4], const float a[4], const float b[2]) {
    asm volatile(
        "mma.sync.aligned.m16n8k8.row.col.f32.tf32.tf32.f32 "
        "{%0,%1,%2,%3}, {%4,%5,%6,%7}, {%8,%9}, {%0,%1,%2,%3};\n"
        : "+f"(c[0]), "+f"(c[1]), "+f"(c[2]), "+f"(c[3])
        : "r"(__float_as_uint(a[0])), "r"(__float_as_uint(a[1])),
          "r"(__float_as_uint(a[2])), "r"(__float_as_uint(a[3])),
          "r"(__float_as_uint(b[0])), "r"(__float_as_uint(b[1])));
}

// ---------------------------------------------------------------------------
// Pre-pass kernels: tf32 rounding (+transpose for weights)
// ---------------------------------------------------------------------------
__global__ __launch_bounds__(256)
void round_copy(const float* __restrict__ src, float* __restrict__ dst)
{
    int i = blockIdx.x * blockDim.x + threadIdx.x;
    float4 v = ((const float4*)src)[i];
    v.x = to_tf32(v.x); v.y = to_tf32(v.y);
    v.z = to_tf32(v.z); v.w = to_tf32(v.w);
    ((float4*)dst)[i] = v;
}

__global__ __launch_bounds__(256)
void transpose_round(const float* __restrict__ W, float* __restrict__ WT, int N)
{
    __shared__ float tile[32][33];
    int n0 = blockIdx.x * 32;
    int k0 = blockIdx.y * 32;
    int tx = threadIdx.x, ty = threadIdx.y;     // 32 x 8
#pragma unroll
    for (int i = ty; i < 32; i += 8)
        tile[i][tx] = W[(size_t)(k0 + i) * N + n0 + tx];
    __syncthreads();
#pragma unroll
    for (int i = ty; i < 32; i += 8)
        WT[(size_t)(n0 + i) * 1024 + k0 + tx] = to_tf32(tile[tx][i]);
}

// ---------------------------------------------------------------------------
// tf32 mma.sync GEMM: out[M,N] = A[M,1024] @ W[1024,N] + bias
// 128x128 CTA tile, 4 warps of 64x64 output each (mt=4 x nt=8 m16n8k8 tiles),
// BK=16, 3-stage cp.async pipeline, ONE __syncthreads per slab.
// Smem [128][20] fp32 per matrix per stage (pitch 20 -> conflict-free LDS).
// ---------------------------------------------------------------------------
#define PITCH_G 20
#define STG_FLOATS (128 * PITCH_G)                // 2560 floats per matrix
#define GEMM_SMEM  (3 * 2 * STG_FLOATS * 4)       // 61,440 B

template <bool SCATTER>
__global__ __launch_bounds__(128)
void gemm_mma(const float* __restrict__ A, const float* __restrict__ BT,
              const float* __restrict__ bias, float* __restrict__ out)
{
    extern __shared__ float smg[];

    const int tid = threadIdx.x;
    const int wid = tid >> 5;
    const int lane = tid & 31;
    const int wr = wid >> 1;         // 0..1  (64 M rows each)
    const int wc = wid & 1;          // 0..1  (64 N cols each)
    const int c0 = blockIdx.x * 128;
    const int r0 = blockIdx.y * 128;

    const float* Ab = A + (size_t)r0 * 1024;
    const float* Bb = BT + (size_t)c0 * 1024;

    float acc[4][8][4];
#pragma unroll
    for (int mt = 0; mt < 4; mt++)
#pragma unroll
        for (int nt = 0; nt < 8; nt++)
#pragma unroll
            for (int u = 0; u < 4; u++) acc[mt][nt][u] = 0.f;

    // cp.async one BK=16 slab (A+B) into stage st
    auto stage = [&](int c, int st) {
        float* sA = smg + st * 2 * STG_FLOATS;
        float* sB = sA + STG_FLOATS;
        const int k0 = c * 16;
#pragma unroll
        for (int i = 0; i < 4; i++) {
            int slot = tid + i * 128;        // 0..511
            int row = slot >> 2;             // 0..127
            int kq = (slot & 3) * 4;         // 0,4,8,12
            cp16(smem_u32(&sA[row * PITCH_G + kq]),
                 Ab + (size_t)row * 1024 + k0 + kq);
            cp16(smem_u32(&sB[row * PITCH_G + kq]),
                 Bb + (size_t)row * 1024 + k0 + kq);
        }
        CP_COMMIT();
    };

    stage(0, 0);
    stage(1, 1);

    const int lr = lane >> 2;        // 0..7
    const int lk = lane & 3;         // 0..3

    for (int c = 0; c < 64; c++) {
        const int st = c % 3;
        CP_WAIT(1);                  // slab c resident
        __syncthreads();             // visibility + everyone done with stage st
        if (c + 2 < 64) stage(c + 2, (c + 2) % 3);
        else CP_COMMIT();            // keep group accounting aligned

        const float* tA = smg + st * 2 * STG_FLOATS + wr * 64 * PITCH_G;
        const float* tB = smg + st * 2 * STG_FLOATS + STG_FLOATS + wc * 64 * PITCH_G;
#pragma unroll
        for (int ks = 0; ks < 2; ks++) {
            float b[8][2];
#pragma unroll
            for (int nt = 0; nt < 8; nt++) {
                const float* Bn = &tB[(nt * 8 + lr) * PITCH_G + ks * 8];
                b[nt][0] = Bn[lk];
                b[nt][1] = Bn[4 + lk];
            }
#pragma unroll
            for (int mt = 0; mt < 4; mt++) {
                const float* Am = &tA[(mt * 16 + lr) * PITCH_G + ks * 8];
                float a[4];
                a[0] = Am[lk];
                a[1] = Am[8 * PITCH_G + lk];
                a[2] = Am[4 + lk];
                a[3] = Am[8 * PITCH_G + 4 + lk];
#pragma unroll
                for (int nt = 0; nt < 8; nt++)
                    mma_tf32(acc[mt][nt], a, b[nt]);
            }
        }
    }

    // Epilogue
    const int lc = (lane & 3) * 2;
#pragma unroll
    for (int mt = 0; mt < 4; mt++) {
#pragma unroll
        for (int nt = 0; nt < 8; nt++) {
            int m = r0 + wr * 64 + mt * 16 + lr;
            int n = c0 + wc * 64 + nt * 8 + lc;
            float b0 = bias[n], b1 = bias[n + 1];
            float2 v0 = make_float2(acc[mt][nt][0] + b0, acc[mt][nt][1] + b1);
            float2 v1 = make_float2(acc[mt][nt][2] + b0, acc[mt][nt][3] + b1);
            if (SCATTER) {
                int which = n >> 10;
                int cc = n & 1023;
                int h = cc >> 6;
                int d = cc & 63;
                int bb = m >> 11;
                int t = m & 2047;
                float* dst = (which == 0) ? g_q : (which == 1) ? g_k : g_v;
                size_t base = (size_t)(bb * NHEAD + h) * SEQ;
                *(float2*)(dst + (base + t) * DHEAD + d) = v0;
                *(float2*)(dst + (base + t + 8) * DHEAD + d) = v1;
            } else {
                *(float2*)(out + (size_t)m * 1024 + n) = v0;
                *(float2*)(out + (size_t)(m + 8) * 1024 + n) = v1;
            }
        }
    }
}

// ---------------------------------------------------------------------------
// Tensor-core flash attention (tf32 mma.sync)
// grid (16, 64): one CTA per (q-tile of 128 rows, bh). 8 warps x 16 Q rows.
// K/V double-buffered via cp.async (unrounded; tf32 MMA truncates mantissa).
// P round-trips through per-warp-private smem (only __syncwarp needed).
// ---------------------------------------------------------------------------
#define AP 68
#define SMEM_ATTN ((2 * 64 + 2 * 64 + 128) * AP * 4)   // 104,448 B

__global__ __launch_bounds__(256)
void attn_mma()
{
    extern __shared__ float sm[];
    float* sK[2] = {sm, sm + 64 * AP};
    float* sV[2] = {sm + 2 * 64 * AP, sm + 3 * 64 * AP};
    float* sP = sm + 4 * 64 * AP;     // [128][AP] per-warp-private rows

    const int qi = (int)gridDim.x - 1 - (int)blockIdx.x;   // heavy tiles first
    const int bh = blockIdx.y;
    const int tid = threadIdx.x;
    const int wid = tid >> 5;
    const int lane = tid & 31;
    const int lr = lane >> 2;        // 0..7
    const int lk = lane & 3;         // 0..3
    const int warp_m = wid * 16;
    const int q0 = qi * 128;

    const float* Kg = g_k + (size_t)bh * SEQ * DHEAD;
    const float* Vg = g_v + (size_t)bh * SEQ * DHEAD;

    // stage K/V tile kt into buffer b (cp.async; 4+4 float4 per thread)
    auto stage = [&](int kt, int b) {
        const int k0 = kt * 64;
#pragma unroll
        for (int i = 0; i < 4; i++) {
            int slot = tid + i * 256;        // 0..1023
            int row = slot >> 4;             // 0..63
            int c4 = (slot & 15) * 4;        // 0..60
            cp16(smem_u32(&sK[b][row * AP + c4]), Kg + (size_t)(k0 + row) * 64 + c4);
            cp16(smem_u32(&sV[b][row * AP + c4]), Vg + (size_t)(k0 + row) * 64 + c4);
        }
        CP_COMMIT();
    };

    // Q fragments: A-frag per k-step (8 steps of k=8)
    float qf[8][4];
    {
        const float* Qw = g_q + ((size_t)bh * SEQ + q0 + warp_m) * DHEAD;
#pragma unroll
        for (int ks = 0; ks < 8; ks++) {
            qf[ks][0] = to_tf32(Qw[lr * 64 + ks * 8 + lk]);
            qf[ks][1] = to_tf32(Qw[(lr + 8) * 64 + ks * 8 + lk]);
            qf[ks][2] = to_tf32(Qw[lr * 64 + ks * 8 + 4 + lk]);
            qf[ks][3] = to_tf32(Qw[(lr + 8) * 64 + ks * 8 + 4 + lk]);
        }
    }

    float o[8][4];
#pragma unroll
    for (int nt = 0; nt < 8; nt++)
#pragma unroll
        for (int u = 0; u < 4; u++) o[nt][u] = 0.f;

    float m0 = -1e30f, m1 = -1e30f, l0 = 0.f, l1 = 0.f;
    const float scale = 0.125f;      // 1/sqrt(64)
    const int row0 = q0 + warp_m + lr;
    const int row1 = row0 + 8;

    float* Pr0 = &sP[(warp_m + lr) * AP];
    float* Pr1 = &sP[(warp_m + lr + 8) * AP];

    const int nkt = (qi + 1) * 2;
    stage(0, 0);

    for (int kt = 0; kt < nkt; kt++) {
        const int buf = kt & 1;
        const int k0 = kt * 64;

        __syncthreads();             // all warps done with buf^1 (prev compute)
        if (kt + 1 < nkt) stage(kt + 1, buf ^ 1);
        else CP_COMMIT();
        CP_WAIT(1);                  // tile kt resident
        __syncthreads();             // visibility

        // Warps fully above the diagonal of this K tile have nothing to do
        if (k0 > q0 + warp_m + 15) continue;

        const float* cK = sK[buf];
        const float* cV = sV[buf];

        // S = Q K^T   (16 x 64 per warp)
        float s[8][4];
#pragma unroll
        for (int nt = 0; nt < 8; nt++)
#pragma unroll
            for (int u = 0; u < 4; u++) s[nt][u] = 0.f;

#pragma unroll
        for (int nt = 0; nt < 8; nt++) {
            const float* Kn = &cK[(nt * 8 + lr) * AP];
#pragma unroll
            for (int ks = 0; ks < 8; ks++) {
                float b[2] = {Kn[ks * 8 + lk], Kn[ks * 8 + 4 + lk]};
                mma_tf32(s[nt], qf[ks], b);
            }
        }

        // Scale + causal mask + row max
        const bool need_mask = (k0 + 63 > row0);
        float rmax0 = -1e30f, rmax1 = -1e30f;
#pragma unroll
        for (int nt = 0; nt < 8; nt++) {
            const int cb = k0 + nt * 8 + 2 * lk;
            if (need_mask) {
                s[nt][0] = (cb     > row0) ? -1e30f : s[nt][0] * scale;
                s[nt][1] = (cb + 1 > row0) ? -1e30f : s[nt][1] * scale;
                s[nt][2] = (cb     > row1) ? -1e30f : s[nt][2] * scale;
                s[nt][3] = (cb + 1 > row1) ? -1e30f : s[nt][3] * scale;
            } else {
                s[nt][0] *= scale; s[nt][1] *= scale;
                s[nt][2] *= scale; s[nt][3] *= scale;
            }
            rmax0 = fmaxf(rmax0, fmaxf(s[nt][0], s[nt][1]));
            rmax1 = fmaxf(rmax1, fmaxf(s[nt][2], s[nt][3]));
        }
        rmax0 = fmaxf(rmax0, __shfl_xor_sync(0xffffffffu, rmax0, 1));
        rmax0 = fmaxf(rmax0, __shfl_xor_sync(0xffffffffu, rmax0, 2));
        rmax1 = fmaxf(rmax1, __shfl_xor_sync(0xffffffffu, rmax1, 1));
        rmax1 = fmaxf(rmax1, __shfl_xor_sync(0xffffffffu, rmax1, 2));

        const float mn0 = fmaxf(m0, rmax0);
        const float mn1 = fmaxf(m1, rmax1);
        const float a0 = __expf(m0 - mn0);
        const float a1 = __expf(m1 - mn1);
        m0 = mn0; m1 = mn1;

        float rs0 = 0.f, rs1 = 0.f;
#pragma unroll
        for (int nt = 0; nt < 8; nt++) {
            s[nt][0] = __expf(s[nt][0] - mn0);
            s[nt][1] = __expf(s[nt][1] - mn0);
            s[nt][2] = __expf(s[nt][2] - mn1);
            s[nt][3] = __expf(s[nt][3] - mn1);
            rs0 += s[nt][0] + s[nt][1];
            rs1 += s[nt][2] + s[nt][3];
        }
        rs0 += __shfl_xor_sync(0xffffffffu, rs0, 1);
        rs0 += __shfl_xor_sync(0xffffffffu, rs0, 2);
        rs1 += __shfl_xor_sync(0xffffffffu, rs1, 1);
        rs1 += __shfl_xor_sync(0xffffffffu, rs1, 2);
        l0 = l0 * a0 + rs0;
        l1 = l1 * a1 + rs1;

#pragma unroll
        for (int nt = 0; nt < 8; nt++) {
            o[nt][0] *= a0; o[nt][1] *= a0;
            o[nt][2] *= a1; o[nt][3] *= a1;
        }

        // P -> per-warp-private smem strip (tf32-rounded)
#pragma unroll
        for (int nt = 0; nt < 8; nt++) {
            *(float2*)&Pr0[nt * 8 + 2 * lk] =
                make_float2(to_tf32(s[nt][0]), to_tf32(s[nt][1]));
            *(float2*)&Pr1[nt * 8 + 2 * lk] =
                make_float2(to_tf32(s[nt][2]), to_tf32(s[nt][3]));
        }
        __syncwarp();

        // O += P @ V
#pragma unroll
        for (int ks = 0; ks < 8; ks++) {
            float ap[4];
            ap[0] = Pr0[ks * 8 + lk];
            ap[1] = Pr1[ks * 8 + lk];
            ap[2] = Pr0[ks * 8 + 4 + lk];
            ap[3] = Pr1[ks * 8 + 4 + lk];
#pragma unroll
            for (int nt = 0; nt < 8; nt++) {
                float b[2] = {cV[(ks * 8 + lk) * AP + nt * 8 + lr],
                              cV[(ks * 8 + 4 + lk) * AP + nt * 8 + lr]};
                mma_tf32(o[nt], ap, b);
            }
        }
        __syncwarp();
    }

    // Epilogue: normalize, tf32-round (feeds tf32 proj GEMM), write [B,T,C]
    const float inv0 = 1.f / l0;
    const float inv1 = 1.f / l1;
    const int b = bh >> 4;
    const int h = bh & 15;
    float* y0 = g_y + ((size_t)(b * SEQ + row0)) * CDIM + h * 64;
    float* y1 = g_y + ((size_t)(b * SEQ + row1)) * CDIM + h * 64;
#pragma unroll
    for (int nt = 0; nt < 8; nt++) {
        int d = nt * 8 + 2 * lk;
        *(float2*)(y0 + d) = make_float2(to_tf32(o[nt][0] * inv0),
                                         to_tf32(o[nt][1] * inv0));
        *(float2*)(y1 + d) = make_float2(to_tf32(o[nt][2] * inv1),
                                         to_tf32(o[nt][3] * inv1));
    }
}

// ---------------------------------------------------------------------------
extern "C" void kernel_launch(void* const* d_in, const int* in_sizes, int n_in,
                              void* d_out, int out_size)
{
    const float* x      = (const float*)d_in[0];
    const float* w_attn = (const float*)d_in[1];
    const float* b_attn = (const float*)d_in[2];
    const float* w_proj = (const float*)d_in[3];
    const float* b_proj = (const float*)d_in[4];
    float* out = (float*)d_out;

    cudaFuncSetAttribute(attn_mma, cudaFuncAttributeMaxDynamicSharedMemorySize,
                         SMEM_ATTN);
    cudaFuncSetAttribute(gemm_mma<true>, cudaFuncAttributeMaxDynamicSharedMemorySize,
                         GEMM_SMEM);
    cudaFuncSetAttribute(gemm_mma<false>, cudaFuncAttributeMaxDynamicSharedMemorySize,
                         GEMM_SMEM);

    void* y_ptr = nullptr;   cudaGetSymbolAddress(&y_ptr, g_y);
    void* xr_ptr = nullptr;  cudaGetSymbolAddress(&xr_ptr, g_xr);
    void* wt1_ptr = nullptr; cudaGetSymbolAddress(&wt1_ptr, g_wt1);
    void* wt2_ptr = nullptr; cudaGetSymbolAddress(&wt2_ptr, g_wt2);

    // 0) tf32-round x; transpose + round weights
    round_copy<<<(MROWS * CDIM / 4) / 256, 256>>>(x, (float*)xr_ptr);
    transpose_round<<<dim3(3072 / 32, 1024 / 32), dim3(32, 8)>>>(w_attn, (float*)wt1_ptr, 3072);
    transpose_round<<<dim3(1024 / 32, 1024 / 32), dim3(32, 8)>>>(w_proj, (float*)wt2_ptr, 1024);

    // 1) QKV projection (tf32 mma) + scatter to [BH][T][D]
    gemm_mma<true><<<dim3(3072 / 128, MROWS / 128), 128, GEMM_SMEM>>>(
        (const float*)xr_ptr, (const float*)wt1_ptr, b_attn, nullptr);

    // 2) Causal flash attention (tf32 mma)
    attn_mma<<<dim3(SEQ / 128, BH), 256, SMEM_ATTN>>>();

    // 3) Output projection (tf32 mma)
    gemm_mma<false><<<dim3(1024 / 128, MROWS / 128), 128, GEMM_SMEM>>>(
        (const float*)y_ptr, (const float*)wt2_ptr, b_proj, out);
}